// round 13
// baseline (speedup 1.0000x reference)
#include <cuda_runtime.h>
#include <math.h>

#define BATCH 2048
#define T 50
#define D 256
#define NEGC (-100000.0f)
#define INV_SQRT_D 0.0625f
#define NSK 4            // split-K slices
#define KSL 64           // k per slice
#define GRID_ATTN 296    // 2 CTAs per SM, persistent

typedef unsigned long long u64;

// ---------------- device scratch ----------------
__device__ float g_Aqk[D * D];
__device__ float g_u[D];
__device__ float g_qrs[D];
__device__ float g_wv[D];
__device__ float g_ksum[D];
__device__ float g_scal[3];
__device__ float g_Z[BATCH * D];
__device__ float g_Yp[NSK * BATCH * D];   // split-K partials of Y
__device__ float g_Op[NSK * BATCH * D];   // split-K partials of out

// ---------------- f32x2 helpers ----------------
__device__ __forceinline__ void ffma2(u64& d, u64 a, u64 b) {
    asm("fma.rn.f32x2 %0, %1, %2, %0;" : "+l"(d) : "l"(a), "l"(b));
}
__device__ __forceinline__ float2 unpack2(u64 v) {
    float2 r;
    asm("mov.b64 {%0, %1}, %2;" : "=f"(r.x), "=f"(r.y) : "l"(v));
    return r;
}
__device__ __forceinline__ u64 pack_dup(float v) {
    u64 r;
    asm("mov.b64 %0, {%1, %1};" : "=l"(r) : "f"(v));
    return r;
}
__device__ __forceinline__ float dot4(float4 a, float4 b) {
    return a.x * b.x + a.y * b.y + a.z * b.z + a.w * b.w;
}
__device__ __forceinline__ unsigned smem_u32(const void* p) {
    unsigned a;
    asm("{ .reg .u64 t; cvta.to.shared.u64 t, %1; cvt.u32.u64 %0, t; }" : "=r"(a) : "l"(p));
    return a;
}
__device__ __forceinline__ void mbar_wait(unsigned mbar_a, int parity) {
    unsigned done;
    asm volatile(
        "{\n\t.reg .pred p;\n\t"
        "mbarrier.try_wait.parity.acquire.cta.shared::cta.b64 p, [%1], %2;\n\t"
        "selp.b32 %0, 1, 0, p;\n\t}"
        : "=r"(done) : "r"(mbar_a), "r"(parity) : "memory");
    if (!done) {
        asm volatile(
            "{\n\t.reg .pred P1;\n\t"
            "WL_%=:\n\t"
            "mbarrier.try_wait.parity.acquire.cta.shared::cta.b64 P1, [%0], %1, 0x989680;\n\t"
            "@P1 bra.uni WD_%=;\n\t"
            "bra.uni WL_%=;\n\t"
            "WD_%=:\n\t}"
            :: "r"(mbar_a), "r"(parity) : "memory");
    }
}

// ---------------- K1: prep (Aqk + small vectors), grid 16x16 ----------------
__global__ __launch_bounds__(256) void prep_kernel(const float* __restrict__ Wq,
                                                   const float* __restrict__ bq,
                                                   const float* __restrict__ Wk,
                                                   const float* __restrict__ bk) {
    __shared__ __align__(16) float Aw[256 * 16];
    __shared__ __align__(16) float Bw[256 * 16];
    __shared__ float s_bq[256], s_bk[256];
    int tid = threadIdx.x;
    int tx = tid & 15, ty = tid >> 4;
    int m0 = blockIdx.y * 16, n0 = blockIdx.x * 16;

    int e0 = tid >> 2, q = tid & 3;
    #pragma unroll
    for (int j = 0; j < 4; j++) {
        int e = e0 + 64 * j;
        float4 a = *(const float4*)(Wq + (size_t)e * D + m0 + q * 4);
        float4 b = *(const float4*)(Wk + (size_t)e * D + n0 + q * 4);
        *(float4*)&Aw[e * 16 + q * 4] = a;
        *(float4*)&Bw[e * 16 + q * 4] = b;
    }
    s_bq[tid] = bq[tid];
    s_bk[tid] = bk[tid];
    __syncthreads();

    float acc = 0.f;
    #pragma unroll 8
    for (int e = 0; e < 256; e++) acc += Aw[e * 16 + ty] * Bw[e * 16 + tx];
    g_Aqk[(m0 + ty) * D + n0 + tx] = acc;

    if (blockIdx.x == 0 && ty == 0) {
        float su = 0.f, sq = 0.f;
        #pragma unroll 8
        for (int e = 0; e < 256; e++) {
            float w = Aw[e * 16 + tx];
            su += s_bk[e] * w;
            sq += w;
        }
        g_u[m0 + tx] = su;
        g_qrs[m0 + tx] = sq;
    }
    if (blockIdx.y == 0 && ty == 1) {
        float sw = 0.f, sk = 0.f;
        #pragma unroll 8
        for (int e = 0; e < 256; e++) {
            float w = Bw[e * 16 + tx];
            sw += s_bq[e] * w;
            sk += w;
        }
        g_wv[n0 + tx] = sw;
        g_ksum[n0 + tx] = sk;
    }
    if (blockIdx.x == 0 && blockIdx.y == 0 && tid < 32) {
        float a0 = 0.f, a1 = 0.f, a2 = 0.f;
        #pragma unroll
        for (int j = 0; j < 8; j++) {
            float qv = s_bq[tid + 32 * j], kv = s_bk[tid + 32 * j];
            a0 += qv * kv; a1 += qv; a2 += kv;
        }
        #pragma unroll
        for (int o = 16; o > 0; o >>= 1) {
            a0 += __shfl_xor_sync(0xffffffffu, a0, o);
            a1 += __shfl_xor_sync(0xffffffffu, a1, o);
            a2 += __shfl_xor_sync(0xffffffffu, a2, o);
        }
        if (tid == 0) { g_scal[0] = a0; g_scal[1] = a1; g_scal[2] = a2; }
    }
}

// ---------------- split-K GEMM: 128m x 64n x 64k per CTA, grid (4,16,4) ----------------
template <int ASRC, int BSRC, int PDST>
__global__ __launch_bounds__(256) void gemm_sk(const float* __restrict__ x,
                                               const float* __restrict__ td,
                                               const float* __restrict__ Bp) {
    __shared__ __align__(16) float As[KSL * 128];  // [k][m] 32KB
    __shared__ __align__(16) float Bs[KSL * 64];   // [k][n] 16KB
    int tid = threadIdx.x;
    int n0 = blockIdx.x * 64, m0 = blockIdx.y * 128, ks = blockIdx.z * KSL;

    {
        int r = tid & 127, kc = (tid >> 7) * 32;
        const float* arow;
        float asc = 1.0f;
        if (ASRC == 0) {
            int gb = m0 + r;
            arow = x + ((size_t)gb * T + (T - 1)) * D;
            asc = td[gb * T + (T - 1)];
        } else {
            arow = g_Z + (size_t)(m0 + r) * D;
        }
        float4 v[8];
        #pragma unroll
        for (int i = 0; i < 8; i++) v[i] = *(const float4*)(arow + ks + kc + i * 4);
        #pragma unroll
        for (int i = 0; i < 8; i++) {
            As[(kc + i * 4 + 0) * 128 + r] = v[i].x * asc;
            As[(kc + i * 4 + 1) * 128 + r] = v[i].y * asc;
            As[(kc + i * 4 + 2) * 128 + r] = v[i].z * asc;
            As[(kc + i * 4 + 3) * 128 + r] = v[i].w * asc;
        }
    }
    if (BSRC == 0) {
        int q = tid & 15, kr0 = tid >> 4;
        #pragma unroll
        for (int p = 0; p < 4; p++) {
            int kr = kr0 + p * 16;
            float4 v = *(const float4*)(g_Aqk + (size_t)(ks + kr) * D + n0 + q * 4);
            *(float4*)&Bs[kr * 64 + q * 4] = v;
        }
    } else {
        int nr = tid & 63, kq = (tid >> 6) * 16;
        const float* brow = Bp + (size_t)(n0 + nr) * D + ks + kq;
        float4 v0 = *(const float4*)(brow);
        float4 v1 = *(const float4*)(brow + 4);
        float4 v2 = *(const float4*)(brow + 8);
        float4 v3 = *(const float4*)(brow + 12);
        float vs[16] = {v0.x, v0.y, v0.z, v0.w, v1.x, v1.y, v1.z, v1.w,
                        v2.x, v2.y, v2.z, v2.w, v3.x, v3.y, v3.z, v3.w};
        #pragma unroll
        for (int i = 0; i < 16; i++) Bs[(kq + i) * 64 + nr] = vs[i];
    }
    __syncthreads();

    int tx = tid & 15, ty = tid >> 4;
    u64 acc[4][4] = {};
    #pragma unroll 2
    for (int kk = 0; kk < KSL; kk += 16) {
        #pragma unroll
        for (int k2 = 0; k2 < 16; k2++) {
            int k = kk + k2;
            ulonglong2 a01 = *(const ulonglong2*)&As[k * 128 + ty * 8];
            ulonglong2 a23 = *(const ulonglong2*)&As[k * 128 + ty * 8 + 4];
            float4 b4 = *(const float4*)&Bs[k * 64 + tx * 4];
            u64 b0 = pack_dup(b4.x), b1 = pack_dup(b4.y);
            u64 b2 = pack_dup(b4.z), b3 = pack_dup(b4.w);
            ffma2(acc[0][0], a01.x, b0); ffma2(acc[0][1], a01.x, b1);
            ffma2(acc[0][2], a01.x, b2); ffma2(acc[0][3], a01.x, b3);
            ffma2(acc[1][0], a01.y, b0); ffma2(acc[1][1], a01.y, b1);
            ffma2(acc[1][2], a01.y, b2); ffma2(acc[1][3], a01.y, b3);
            ffma2(acc[2][0], a23.x, b0); ffma2(acc[2][1], a23.x, b1);
            ffma2(acc[2][2], a23.x, b2); ffma2(acc[2][3], a23.x, b3);
            ffma2(acc[3][0], a23.y, b0); ffma2(acc[3][1], a23.y, b1);
            ffma2(acc[3][2], a23.y, b2); ffma2(acc[3][3], a23.y, b3);
        }
    }

    float* part = (PDST == 0) ? g_Yp : g_Op;
    int gn = n0 + tx * 4;
    int gmb = m0 + ty * 8;
    size_t base = ((size_t)blockIdx.z * BATCH + gmb) * D + gn;
    #pragma unroll
    for (int mp = 0; mp < 4; mp++) {
        float2 p0 = unpack2(acc[mp][0]), p1 = unpack2(acc[mp][1]);
        float2 p2 = unpack2(acc[mp][2]), p3 = unpack2(acc[mp][3]);
        *(float4*)&part[base + (size_t)(2 * mp) * D] = make_float4(p0.x, p1.x, p2.x, p3.x);
        *(float4*)&part[base + (size_t)(2 * mp + 1) * D] = make_float4(p0.y, p1.y, p2.y, p3.y);
    }
}

// ---------------- K3: attn — persistent, double-buffered TMA ----------------
__global__ __launch_bounds__(256, 2) void attn_kernel(const float* __restrict__ x,
                                                      const int* __restrict__ mask,
                                                      const float* __restrict__ td) {
    extern __shared__ __align__(128) float sm[];
    u64* mbar = (u64*)sm;                 // 2 barriers in first 128B
    float* smx0 = sm + 32;                // 2 x-tile slots, T*D floats each
    float* smV  = sm + 32 + 2 * T * D;    // 256
    float* smtd = smV + D;                // 64
    float* smDV = smtd + 64;              // 64 (50,51 hold dU,dQ)
    float* smw  = smDV + 64;              // 64
    int*   smm  = (int*)(smw + 64);       // 64

    int tid = threadIdx.x;
    int warp = tid >> 5, lane = tid & 31;
    const int XBYTES = T * D * 4;         // 51200

    unsigned mb_a0 = smem_u32(&mbar[0]);
    unsigned mb_a1 = smem_u32(&mbar[1]);
    unsigned smx_a0 = smem_u32(smx0);

    if (tid == 0) {
        asm volatile("mbarrier.init.shared.b64 [%0], 1;" :: "r"(mb_a0) : "memory");
        asm volatile("mbarrier.init.shared.b64 [%0], 1;" :: "r"(mb_a1) : "memory");
        asm volatile("fence.proxy.async.shared::cta;" ::: "memory");
    }
    __syncthreads();

    // prologue TMA for first batch into slot 0
    int b0 = blockIdx.x;
    if (tid == 0) {
        asm volatile("mbarrier.arrive.expect_tx.shared.b64 _, [%0], %1;"
                     :: "r"(mb_a0), "r"(XBYTES) : "memory");
        asm volatile("cp.async.bulk.shared::cta.global.mbarrier::complete_tx::bytes "
                     "[%0], [%1], %2, [%3];"
                     :: "r"(smx_a0), "l"(x + (size_t)b0 * T * D), "r"(XBYTES), "r"(mb_a0)
                     : "memory");
    }

    int it = 0;
    for (int b = b0; b < BATCH; b += GRID_ATTN, it++) {
        int slot = it & 1;
        int parity = (it >> 1) & 1;
        float* smx = smx0 + slot * (T * D);
        unsigned mb_cur = slot ? mb_a1 : mb_a0;

        // prefetch next batch into the other slot (its previous compute is done)
        int bn = b + GRID_ATTN;
        if (tid == 0 && bn < BATCH) {
            unsigned mb_nxt = slot ? mb_a0 : mb_a1;
            unsigned smx_nxt = smx_a0 + (unsigned)((slot ^ 1) * T * D * 4);
            asm volatile("fence.proxy.async.shared::cta;" ::: "memory");
            asm volatile("mbarrier.arrive.expect_tx.shared.b64 _, [%0], %1;"
                         :: "r"(mb_nxt), "r"(XBYTES) : "memory");
            asm volatile("cp.async.bulk.shared::cta.global.mbarrier::complete_tx::bytes "
                         "[%0], [%1], %2, [%3];"
                         :: "r"(smx_nxt), "l"(x + (size_t)bn * T * D), "r"(XBYTES), "r"(mb_nxt)
                         : "memory");
        }

        // per-batch small fills overlap the in-flight TMA
        int mq = __ldg(mask + b * T + (T - 1));
        if (mq) {
            int idx = b * D + tid;
            float s = g_wv[tid];
            #pragma unroll
            for (int j = 0; j < NSK; j++) s += g_Yp[(size_t)j * BATCH * D + idx];
            smV[tid] = s;
        } else {
            smV[tid] = g_ksum[tid];
        }
        if (tid < T) {
            smtd[tid] = td[b * T + tid];
            smm[tid] = mask[b * T + tid];
        }
        __syncthreads();

        mbar_wait(mb_cur, parity);

        float4* smx4 = (float4*)smx;
        float4 va = ((const float4*)smV)[lane];
        float4 vb = ((const float4*)smV)[lane + 32];
        for (int s = warp; s < T; s += 8) {
            float4 x1 = smx4[s * 64 + lane];
            float4 x2 = smx4[s * 64 + 32 + lane];
            float dv = dot4(x1, va) + dot4(x2, vb);
            #pragma unroll
            for (int o = 16; o > 0; o >>= 1) dv += __shfl_xor_sync(0xffffffffu, dv, o);
            if (lane == 0) smDV[s] = dv;
        }
        if (warp == 2 || warp == 3) {
            const float4* w4 = (warp == 2) ? (const float4*)g_u : (const float4*)g_qrs;
            float4 x1 = smx4[(T - 1) * 64 + lane];
            float4 x2 = smx4[(T - 1) * 64 + 32 + lane];
            float dv = dot4(x1, __ldg(w4 + lane)) + dot4(x2, __ldg(w4 + lane + 32));
            #pragma unroll
            for (int o = 16; o > 0; o >>= 1) dv += __shfl_xor_sync(0xffffffffu, dv, o);
            if (lane == 0) smDV[T + (warp - 2)] = dv;
        }
        __syncthreads();

        if (warp == 0) {
            float tdl = smtd[T - 1];
            float s1b = tdl * smDV[T] + g_scal[0];
            float s2b = tdl * smDV[T + 1] + g_scal[1];
            float bksum = g_scal[2];
            float v1 = -3.0e38f, v2 = -3.0e38f;
            if (lane < T) {
                int ms = smm[lane];
                float tds = smtd[lane];
                if (mq) v1 = ms ? (tds * smDV[lane] + s1b) : (NEGC * s2b);
                else    v1 = ms ? (NEGC * (tds * smDV[lane] + bksum)) : (NEGC * NEGC * (float)D);
                v1 *= INV_SQRT_D;
            }
            if (lane + 32 < T) {
                int s = lane + 32;
                int ms = smm[s];
                float tds = smtd[s];
                if (mq) v2 = ms ? (tds * smDV[s] + s1b) : (NEGC * s2b);
                else    v2 = ms ? (NEGC * (tds * smDV[s] + bksum)) : (NEGC * NEGC * (float)D);
                v2 *= INV_SQRT_D;
            }
            float m = fmaxf(v1, v2);
            #pragma unroll
            for (int o = 16; o > 0; o >>= 1) m = fmaxf(m, __shfl_xor_sync(0xffffffffu, m, o));
            float e1 = (lane < T) ? expf(v1 - m) : 0.f;
            float e2 = (lane + 32 < T) ? expf(v2 - m) : 0.f;
            float es = e1 + e2;
            #pragma unroll
            for (int o = 16; o > 0; o >>= 1) es += __shfl_xor_sync(0xffffffffu, es, o);
            float inv = 1.0f / es;
            if (lane < T) smw[lane] = e1 * inv * smtd[lane];
            if (lane + 32 < T) smw[lane + 32] = e2 * inv * smtd[lane + 32];
        }
        __syncthreads();

        int g = tid >> 6, q = tid & 63;
        float4 acc = make_float4(0.f, 0.f, 0.f, 0.f);
        for (int s = g; s < T; s += 4) {
            float w = smw[s];
            float4 xv = smx4[s * 64 + q];
            acc.x += w * xv.x; acc.y += w * xv.y; acc.z += w * xv.z; acc.w += w * xv.w;
        }
        __syncthreads();
        smx4[g * 64 + q] = acc;        // partials overlay current slot
        __syncthreads();
        if (tid < 64) {
            float4 p0 = smx4[tid], p1 = smx4[64 + tid];
            float4 p2 = smx4[128 + tid], p3 = smx4[192 + tid];
            float4 r = make_float4(p0.x + p1.x + p2.x + p3.x, p0.y + p1.y + p2.y + p3.y,
                                   p0.z + p1.z + p2.z + p3.z, p0.w + p1.w + p2.w + p3.w);
            ((float4*)(g_Z + (size_t)b * D))[tid] = r;
        }
        __syncthreads();               // slot fully consumed before its next TMA
    }
}

// ---------------- K5: reduce out partials + bias ----------------
__global__ __launch_bounds__(256) void reduce_out(const float* __restrict__ bv,
                                                  float* __restrict__ out) {
    int i = blockIdx.x * 256 + threadIdx.x;
    const float4* p = (const float4*)g_Op;
    const int Q = BATCH * D / 4;
    float4 bb = ((const float4*)bv)[i & 63];
    float4 r = bb;
    #pragma unroll
    for (int j = 0; j < NSK; j++) {
        float4 a = p[i + (size_t)j * Q];
        r.x += a.x; r.y += a.y; r.z += a.z; r.w += a.w;
    }
    ((float4*)out)[i] = r;
}

// ---------------- launch ----------------
extern "C" void kernel_launch(void* const* d_in, const int* in_sizes, int n_in,
                              void* d_out, int out_size) {
    const float* x = (const float*)d_in[0];
    const int* mask = (const int*)d_in[1];
    const float* td = (const float*)d_in[2];
    const float* Wq = (const float*)d_in[3];
    const float* bq = (const float*)d_in[4];
    const float* Wk = (const float*)d_in[5];
    const float* bk = (const float*)d_in[6];
    const float* Wv = (const float*)d_in[7];
    const float* bv = (const float*)d_in[8];
    float* out = (float*)d_out;

    // 128B mbar block + 2 x-tile slots + small arrays
    const int attn_smem = (32 + 2 * T * D + D + 64 + 64 + 64 + 64) * 4;  // ~102.1 KB
    cudaFuncSetAttribute(attn_kernel, cudaFuncAttributeMaxDynamicSharedMemorySize, attn_smem);

    dim3 gsk(4, 16, NSK);
    prep_kernel<<<dim3(16, 16), 256>>>(Wq, bq, Wk, bk);
    gemm_sk<0, 0, 0><<<gsk, 256>>>(x, td, nullptr);        // Y partials
    attn_kernel<<<GRID_ATTN, 256, attn_smem>>>(x, mask, td);
    gemm_sk<1, 1, 1><<<gsk, 256>>>(nullptr, nullptr, Wv);  // out partials
    reduce_out<<<BATCH * D / 4 / 256, 256>>>(bv, out);
}

// round 15
// speedup vs baseline: 1.1255x; 1.1255x over previous
#include <cuda_runtime.h>
#include <math.h>

#define BATCH 2048
#define T 50
#define D 256
#define NEGC (-100000.0f)
#define INV_SQRT_D 0.0625f
#define NSK 4            // split-K slices
#define KSL 64           // k per slice

typedef unsigned long long u64;

// ---------------- device scratch ----------------
__device__ float g_Aqk[D * D];
__device__ float g_u[D];
__device__ float g_qrs[D];
__device__ float g_wv[D];
__device__ float g_ksum[D];
__device__ float g_scal[3];
__device__ float g_Z[BATCH * D];
__device__ float g_Yp[NSK * BATCH * D];   // split-K partials of Y

// ---------------- stream/event infra (created at load, before capture) ----------------
namespace {
struct Infra {
    cudaStream_t s1;
    cudaEvent_t evRoot, evI;
    Infra() {
        cudaStreamCreateWithFlags(&s1, cudaStreamNonBlocking);
        cudaEventCreateWithFlags(&evRoot, cudaEventDisableTiming);
        cudaEventCreateWithFlags(&evI, cudaEventDisableTiming);
    }
};
Infra g_infra;
}

// ---------------- helpers ----------------
__device__ __forceinline__ void ffma2(u64& d, u64 a, u64 b) {
    asm("fma.rn.f32x2 %0, %1, %2, %0;" : "+l"(d) : "l"(a), "l"(b));
}
__device__ __forceinline__ float2 unpack2(u64 v) {
    float2 r;
    asm("mov.b64 {%0, %1}, %2;" : "=f"(r.x), "=f"(r.y) : "l"(v));
    return r;
}
__device__ __forceinline__ u64 pack_dup(float v) {
    u64 r;
    asm("mov.b64 %0, {%1, %1};" : "=l"(r) : "f"(v));
    return r;
}
__device__ __forceinline__ float dot4(float4 a, float4 b) {
    return a.x * b.x + a.y * b.y + a.z * b.z + a.w * b.w;
}
__device__ __forceinline__ unsigned smem_u32(const void* p) {
    unsigned a;
    asm("{ .reg .u64 t; cvta.to.shared.u64 t, %1; cvt.u32.u64 %0, t; }" : "=r"(a) : "l"(p));
    return a;
}
__device__ __forceinline__ void redg_v4(float* p, float a, float b, float c, float d) {
    asm volatile("red.global.add.v4.f32 [%0], {%1, %2, %3, %4};"
                 :: "l"(p), "f"(a), "f"(b), "f"(c), "f"(d) : "memory");
}

// ---------------- K0: init out with bias (overlapped on s1) ----------------
__global__ __launch_bounds__(256) void init_out(const float* __restrict__ bv,
                                                float* __restrict__ out) {
    int i = blockIdx.x * 256 + threadIdx.x;
    ((float4*)out)[i] = ((const float4*)bv)[i & 63];
}

// ---------------- K1: prep (Aqk + small vectors), grid 16x16 ----------------
__global__ __launch_bounds__(256) void prep_kernel(const float* __restrict__ Wq,
                                                   const float* __restrict__ bq,
                                                   const float* __restrict__ Wk,
                                                   const float* __restrict__ bk) {
    __shared__ __align__(16) float Aw[256 * 16];
    __shared__ __align__(16) float Bw[256 * 16];
    __shared__ float s_bq[256], s_bk[256];
    int tid = threadIdx.x;
    int tx = tid & 15, ty = tid >> 4;
    int m0 = blockIdx.y * 16, n0 = blockIdx.x * 16;

    int e0 = tid >> 2, q = tid & 3;
    #pragma unroll
    for (int j = 0; j < 4; j++) {
        int e = e0 + 64 * j;
        float4 a = *(const float4*)(Wq + (size_t)e * D + m0 + q * 4);
        float4 b = *(const float4*)(Wk + (size_t)e * D + n0 + q * 4);
        *(float4*)&Aw[e * 16 + q * 4] = a;
        *(float4*)&Bw[e * 16 + q * 4] = b;
    }
    s_bq[tid] = bq[tid];
    s_bk[tid] = bk[tid];
    __syncthreads();

    float acc = 0.f;
    #pragma unroll 8
    for (int e = 0; e < 256; e++) acc += Aw[e * 16 + ty] * Bw[e * 16 + tx];
    g_Aqk[(m0 + ty) * D + n0 + tx] = acc;

    if (blockIdx.x == 0 && ty == 0) {
        float su = 0.f, sq = 0.f;
        #pragma unroll 8
        for (int e = 0; e < 256; e++) {
            float w = Aw[e * 16 + tx];
            su += s_bk[e] * w;
            sq += w;
        }
        g_u[m0 + tx] = su;
        g_qrs[m0 + tx] = sq;
    }
    if (blockIdx.y == 0 && ty == 1) {
        float sw = 0.f, sk = 0.f;
        #pragma unroll 8
        for (int e = 0; e < 256; e++) {
            float w = Bw[e * 16 + tx];
            sw += s_bq[e] * w;
            sk += w;
        }
        g_wv[n0 + tx] = sw;
        g_ksum[n0 + tx] = sk;
    }
    if (blockIdx.x == 0 && blockIdx.y == 0 && tid < 32) {
        float a0 = 0.f, a1 = 0.f, a2 = 0.f;
        #pragma unroll
        for (int j = 0; j < 8; j++) {
            float qv = s_bq[tid + 32 * j], kv = s_bk[tid + 32 * j];
            a0 += qv * kv; a1 += qv; a2 += kv;
        }
        #pragma unroll
        for (int o = 16; o > 0; o >>= 1) {
            a0 += __shfl_xor_sync(0xffffffffu, a0, o);
            a1 += __shfl_xor_sync(0xffffffffu, a1, o);
            a2 += __shfl_xor_sync(0xffffffffu, a2, o);
        }
        if (tid == 0) { g_scal[0] = a0; g_scal[1] = a1; g_scal[2] = a2; }
    }
}

// ---------------- split-K GEMM: 128m x 64n x 64k per CTA, grid (4,16,4) ----------------
// ASRC: 0 = x last rows * td    1 = g_Z
// BSRC: 0 = g_Aqk (NN)         1 = param B (NT, B[n][k])
// PDST: 0 = store g_Yp slices  1 = red.global.add into Cout
template <int ASRC, int BSRC, int PDST>
__global__ __launch_bounds__(256) void gemm_sk(const float* __restrict__ x,
                                               const float* __restrict__ td,
                                               const float* __restrict__ Bp,
                                               float* __restrict__ Cout) {
    __shared__ __align__(16) float As[KSL * 128];  // [k][m] 32KB
    __shared__ __align__(16) float Bs[KSL * 64];   // [k][n] 16KB
    int tid = threadIdx.x;
    int n0 = blockIdx.x * 64, m0 = blockIdx.y * 128, ks = blockIdx.z * KSL;

    // ---- A fill ----
    {
        int r = tid & 127, kc = (tid >> 7) * 32;
        const float* arow;
        float asc = 1.0f;
        if (ASRC == 0) {
            int gb = m0 + r;
            arow = x + ((size_t)gb * T + (T - 1)) * D;
            asc = td[gb * T + (T - 1)];
        } else {
            arow = g_Z + (size_t)(m0 + r) * D;
        }
        float4 v[8];
        #pragma unroll
        for (int i = 0; i < 8; i++) v[i] = *(const float4*)(arow + ks + kc + i * 4);
        #pragma unroll
        for (int i = 0; i < 8; i++) {
            As[(kc + i * 4 + 0) * 128 + r] = v[i].x * asc;
            As[(kc + i * 4 + 1) * 128 + r] = v[i].y * asc;
            As[(kc + i * 4 + 2) * 128 + r] = v[i].z * asc;
            As[(kc + i * 4 + 3) * 128 + r] = v[i].w * asc;
        }
    }
    // ---- B fill ----
    if (BSRC == 0) {
        int q = tid & 15, kr0 = tid >> 4;
        #pragma unroll
        for (int p = 0; p < 4; p++) {
            int kr = kr0 + p * 16;
            float4 v = *(const float4*)(g_Aqk + (size_t)(ks + kr) * D + n0 + q * 4);
            *(float4*)&Bs[kr * 64 + q * 4] = v;
        }
    } else {
        int nr = tid & 63, kq = (tid >> 6) * 16;
        const float* brow = Bp + (size_t)(n0 + nr) * D + ks + kq;
        float4 v0 = *(const float4*)(brow);
        float4 v1 = *(const float4*)(brow + 4);
        float4 v2 = *(const float4*)(brow + 8);
        float4 v3 = *(const float4*)(brow + 12);
        float vs[16] = {v0.x, v0.y, v0.z, v0.w, v1.x, v1.y, v1.z, v1.w,
                        v2.x, v2.y, v2.z, v2.w, v3.x, v3.y, v3.z, v3.w};
        #pragma unroll
        for (int i = 0; i < 16; i++) Bs[(kq + i) * 64 + nr] = vs[i];
    }
    __syncthreads();

    // ---- inner loop: thread tile 8m x 4n, f32x2 over m-pairs ----
    int tx = tid & 15, ty = tid >> 4;
    u64 acc[4][4] = {};
    #pragma unroll 2
    for (int kk = 0; kk < KSL; kk += 16) {
        #pragma unroll
        for (int k2 = 0; k2 < 16; k2++) {
            int k = kk + k2;
            ulonglong2 a01 = *(const ulonglong2*)&As[k * 128 + ty * 8];
            ulonglong2 a23 = *(const ulonglong2*)&As[k * 128 + ty * 8 + 4];
            float4 b4 = *(const float4*)&Bs[k * 64 + tx * 4];
            u64 b0 = pack_dup(b4.x), b1 = pack_dup(b4.y);
            u64 b2 = pack_dup(b4.z), b3 = pack_dup(b4.w);
            ffma2(acc[0][0], a01.x, b0); ffma2(acc[0][1], a01.x, b1);
            ffma2(acc[0][2], a01.x, b2); ffma2(acc[0][3], a01.x, b3);
            ffma2(acc[1][0], a01.y, b0); ffma2(acc[1][1], a01.y, b1);
            ffma2(acc[1][2], a01.y, b2); ffma2(acc[1][3], a01.y, b3);
            ffma2(acc[2][0], a23.x, b0); ffma2(acc[2][1], a23.x, b1);
            ffma2(acc[2][2], a23.x, b2); ffma2(acc[2][3], a23.x, b3);
            ffma2(acc[3][0], a23.y, b0); ffma2(acc[3][1], a23.y, b1);
            ffma2(acc[3][2], a23.y, b2); ffma2(acc[3][3], a23.y, b3);
        }
    }

    int gn = n0 + tx * 4;
    int gmb = m0 + ty * 8;
    if (PDST == 0) {
        size_t base = ((size_t)blockIdx.z * BATCH + gmb) * D + gn;
        #pragma unroll
        for (int mp = 0; mp < 4; mp++) {
            float2 p0 = unpack2(acc[mp][0]), p1 = unpack2(acc[mp][1]);
            float2 p2 = unpack2(acc[mp][2]), p3 = unpack2(acc[mp][3]);
            *(float4*)&g_Yp[base + (size_t)(2 * mp) * D] = make_float4(p0.x, p1.x, p2.x, p3.x);
            *(float4*)&g_Yp[base + (size_t)(2 * mp + 1) * D] = make_float4(p0.y, p1.y, p2.y, p3.y);
        }
    } else {
        size_t base = (size_t)gmb * D + gn;
        #pragma unroll
        for (int mp = 0; mp < 4; mp++) {
            float2 p0 = unpack2(acc[mp][0]), p1 = unpack2(acc[mp][1]);
            float2 p2 = unpack2(acc[mp][2]), p3 = unpack2(acc[mp][3]);
            redg_v4(Cout + base + (size_t)(2 * mp) * D, p0.x, p1.x, p2.x, p3.x);
            redg_v4(Cout + base + (size_t)(2 * mp + 1) * D, p0.y, p1.y, p2.y, p3.y);
        }
    }
}

// ---------------- K3: attn — single-shot TMA bulk-copy x tile ----------------
__global__ __launch_bounds__(256, 4) void attn_kernel(const float* __restrict__ x,
                                                      const int* __restrict__ mask,
                                                      const float* __restrict__ td) {
    extern __shared__ __align__(128) float sm[];
    u64* mbar = (u64*)sm;
    float* smx = sm + 32;            // 50*256 floats, 128B-aligned
    float* smV = smx + T * D;        // 256
    float* smtd = smV + D;           // 64
    float* smDV = smtd + 64;         // 64 (50,51 hold dU,dQ)
    float* smw = smDV + 64;          // 64
    int* smm = (int*)(smw + 64);     // 64

    int b = blockIdx.x, tid = threadIdx.x;
    int warp = tid >> 5, lane = tid & 31;
    const int XBYTES = T * D * 4;    // 51200

    unsigned mbar_a = smem_u32(mbar);
    unsigned smx_a = smem_u32(smx);

    if (tid == 0) {
        asm volatile("mbarrier.init.shared.b64 [%0], 1;" :: "r"(mbar_a) : "memory");
        asm volatile("fence.proxy.async.shared::cta;" ::: "memory");
        asm volatile("mbarrier.arrive.expect_tx.shared.b64 _, [%0], %1;"
                     :: "r"(mbar_a), "r"(XBYTES) : "memory");
        asm volatile("cp.async.bulk.shared::cta.global.mbarrier::complete_tx::bytes "
                     "[%0], [%1], %2, [%3];"
                     :: "r"(smx_a), "l"(x + (size_t)b * T * D), "r"(XBYTES), "r"(mbar_a)
                     : "memory");
    }

    int mq = __ldg(mask + b * T + (T - 1));
    if (mq) {
        int idx = b * D + tid;
        float s = g_wv[tid];
        #pragma unroll
        for (int j = 0; j < NSK; j++) s += g_Yp[(size_t)j * BATCH * D + idx];
        smV[tid] = s;
    } else {
        smV[tid] = g_ksum[tid];
    }
    if (tid < T) {
        smtd[tid] = td[b * T + tid];
        smm[tid] = mask[b * T + tid];
    }
    __syncthreads();

    {
        unsigned done;
        asm volatile(
            "{\n\t.reg .pred p;\n\t"
            "mbarrier.try_wait.parity.acquire.cta.shared::cta.b64 p, [%1], 0;\n\t"
            "selp.b32 %0, 1, 0, p;\n\t}"
            : "=r"(done) : "r"(mbar_a) : "memory");
        if (!done) {
            asm volatile(
                "{\n\t.reg .pred P1;\n\t"
                "WL_%=:\n\t"
                "mbarrier.try_wait.parity.acquire.cta.shared::cta.b64 P1, [%0], 0, 0x989680;\n\t"
                "@P1 bra.uni WD_%=;\n\t"
                "bra.uni WL_%=;\n\t"
                "WD_%=:\n\t}"
                :: "r"(mbar_a) : "memory");
        }
    }

    float4* smx4 = (float4*)smx;
    float4 va = ((const float4*)smV)[lane];
    float4 vb = ((const float4*)smV)[lane + 32];
    for (int s = warp; s < T; s += 8) {
        float4 x1 = smx4[s * 64 + lane];
        float4 x2 = smx4[s * 64 + 32 + lane];
        float dv = dot4(x1, va) + dot4(x2, vb);
        #pragma unroll
        for (int o = 16; o > 0; o >>= 1) dv += __shfl_xor_sync(0xffffffffu, dv, o);
        if (lane == 0) smDV[s] = dv;
    }
    if (warp == 2 || warp == 3) {
        const float4* w4 = (warp == 2) ? (const float4*)g_u : (const float4*)g_qrs;
        float4 x1 = smx4[(T - 1) * 64 + lane];
        float4 x2 = smx4[(T - 1) * 64 + 32 + lane];
        float dv = dot4(x1, __ldg(w4 + lane)) + dot4(x2, __ldg(w4 + lane + 32));
        #pragma unroll
        for (int o = 16; o > 0; o >>= 1) dv += __shfl_xor_sync(0xffffffffu, dv, o);
        if (lane == 0) smDV[T + (warp - 2)] = dv;
    }
    __syncthreads();

    if (warp == 0) {
        float tdl = smtd[T - 1];
        float s1b = tdl * smDV[T] + g_scal[0];
        float s2b = tdl * smDV[T + 1] + g_scal[1];
        float bksum = g_scal[2];
        float v1 = -3.0e38f, v2 = -3.0e38f;
        if (lane < T) {
            int ms = smm[lane];
            float tds = smtd[lane];
            if (mq) v1 = ms ? (tds * smDV[lane] + s1b) : (NEGC * s2b);
            else    v1 = ms ? (NEGC * (tds * smDV[lane] + bksum)) : (NEGC * NEGC * (float)D);
            v1 *= INV_SQRT_D;
        }
        if (lane + 32 < T) {
            int s = lane + 32;
            int ms = smm[s];
            float tds = smtd[s];
            if (mq) v2 = ms ? (tds * smDV[s] + s1b) : (NEGC * s2b);
            else    v2 = ms ? (NEGC * (tds * smDV[s] + bksum)) : (NEGC * NEGC * (float)D);
            v2 *= INV_SQRT_D;
        }
        float m = fmaxf(v1, v2);
        #pragma unroll
        for (int o = 16; o > 0; o >>= 1) m = fmaxf(m, __shfl_xor_sync(0xffffffffu, m, o));
        float e1 = (lane < T) ? expf(v1 - m) : 0.f;
        float e2 = (lane + 32 < T) ? expf(v2 - m) : 0.f;
        float es = e1 + e2;
        #pragma unroll
        for (int o = 16; o > 0; o >>= 1) es += __shfl_xor_sync(0xffffffffu, es, o);
        float inv = 1.0f / es;
        if (lane < T) smw[lane] = e1 * inv * smtd[lane];
        if (lane + 32 < T) smw[lane + 32] = e2 * inv * smtd[lane + 32];
    }
    __syncthreads();

    int g = tid >> 6, q = tid & 63;
    float4 acc = make_float4(0.f, 0.f, 0.f, 0.f);
    for (int s = g; s < T; s += 4) {
        float w = smw[s];
        float4 xv = smx4[s * 64 + q];
        acc.x += w * xv.x; acc.y += w * xv.y; acc.z += w * xv.z; acc.w += w * xv.w;
    }
    __syncthreads();
    smx4[g * 64 + q] = acc;
    __syncthreads();
    if (tid < 64) {
        float4 p0 = smx4[tid], p1 = smx4[64 + tid];
        float4 p2 = smx4[128 + tid], p3 = smx4[192 + tid];
        float4 r = make_float4(p0.x + p1.x + p2.x + p3.x, p0.y + p1.y + p2.y + p3.y,
                               p0.z + p1.z + p2.z + p3.z, p0.w + p1.w + p2.w + p3.w);
        ((float4*)(g_Z + (size_t)b * D))[tid] = r;
    }
}

// ---------------- launch: fork-join graph, REDG epilogue ----------------
extern "C" void kernel_launch(void* const* d_in, const int* in_sizes, int n_in,
                              void* d_out, int out_size) {
    const float* x = (const float*)d_in[0];
    const int* mask = (const int*)d_in[1];
    const float* td = (const float*)d_in[2];
    const float* Wq = (const float*)d_in[3];
    const float* bq = (const float*)d_in[4];
    const float* Wk = (const float*)d_in[5];
    const float* bk = (const float*)d_in[6];
    const float* Wv = (const float*)d_in[7];
    const float* bv = (const float*)d_in[8];
    float* out = (float*)d_out;

    const int attn_smem = (32 + T * D + D + 64 + 64 + 64 + 64) * 4;  // ~53.4 KB
    cudaFuncSetAttribute(attn_kernel, cudaFuncAttributeMaxDynamicSharedMemorySize, attn_smem);

    cudaStream_t s1 = g_infra.s1;
    dim3 gsk(4, 16, NSK);

    // fork: root event on capture stream, s1 waits on it (legal capture fork)
    cudaEventRecord(g_infra.evRoot, 0);
    cudaStreamWaitEvent(s1, g_infra.evRoot, 0);
    init_out<<<BATCH * D / 4 / 256, 256, 0, s1>>>(bv, out);
    cudaEventRecord(g_infra.evI, s1);

    // main chain on capture stream
    prep_kernel<<<dim3(16, 16), 256>>>(Wq, bq, Wk, bk);
    gemm_sk<0, 0, 0><<<gsk, 256>>>(x, td, nullptr, nullptr);      // Y partials
    attn_kernel<<<BATCH, 256, attn_smem>>>(x, mask, td);

    // join: out must be bias-initialized before REDG accumulation
    cudaStreamWaitEvent(0, g_infra.evI, 0);
    gemm_sk<1, 1, 1><<<gsk, 256>>>(nullptr, nullptr, Wv, out);    // REDG into out
}

// round 16
// speedup vs baseline: 1.1331x; 1.0068x over previous
#include <cuda_runtime.h>
#include <math.h>

#define BATCH 2048
#define T 50
#define D 256
#define NEGC (-100000.0f)
#define INV_SQRT_D 0.0625f
#define NSK 4            // split-K slices
#define KSL 64           // k per slice

typedef unsigned long long u64;

// ---------------- device scratch ----------------
__device__ float g_Aqk[D * D];
__device__ float g_u[D];
__device__ float g_qrs[D];
__device__ float g_wv[D];
__device__ float g_ksum[D];
__device__ float g_scal[3];
__device__ float g_Z[BATCH * D];
__device__ float g_Yp[NSK * BATCH * D];   // split-K partials of Y

// ---------------- stream/event infra (created at load, before capture) ----------------
namespace {
struct Infra {
    cudaStream_t s1;
    cudaEvent_t evRoot, evP, ev0, ev1;
    Infra() {
        cudaStreamCreateWithFlags(&s1, cudaStreamNonBlocking);
        cudaEventCreateWithFlags(&evRoot, cudaEventDisableTiming);
        cudaEventCreateWithFlags(&evP, cudaEventDisableTiming);
        cudaEventCreateWithFlags(&ev0, cudaEventDisableTiming);
        cudaEventCreateWithFlags(&ev1, cudaEventDisableTiming);
    }
};
Infra g_infra;
}

// ---------------- helpers ----------------
__device__ __forceinline__ void ffma2(u64& d, u64 a, u64 b) {
    asm("fma.rn.f32x2 %0, %1, %2, %0;" : "+l"(d) : "l"(a), "l"(b));
}
__device__ __forceinline__ float2 unpack2(u64 v) {
    float2 r;
    asm("mov.b64 {%0, %1}, %2;" : "=f"(r.x), "=f"(r.y) : "l"(v));
    return r;
}
__device__ __forceinline__ u64 pack_dup(float v) {
    u64 r;
    asm("mov.b64 %0, {%1, %1};" : "=l"(r) : "f"(v));
    return r;
}
__device__ __forceinline__ float dot4(float4 a, float4 b) {
    return a.x * b.x + a.y * b.y + a.z * b.z + a.w * b.w;
}
__device__ __forceinline__ unsigned smem_u32(const void* p) {
    unsigned a;
    asm("{ .reg .u64 t; cvta.to.shared.u64 t, %1; cvt.u32.u64 %0, t; }" : "=r"(a) : "l"(p));
    return a;
}
__device__ __forceinline__ void redg_v4(float* p, float a, float b, float c, float d) {
    asm volatile("red.global.add.v4.f32 [%0], {%1, %2, %3, %4};"
                 :: "l"(p), "f"(a), "f"(b), "f"(c), "f"(d) : "memory");
}

// ---------------- K0: init out with bias (overlapped on s1) ----------------
__global__ __launch_bounds__(256) void init_out(const float* __restrict__ bv,
                                                float* __restrict__ out) {
    int i = blockIdx.x * 256 + threadIdx.x;
    ((float4*)out)[i] = ((const float4*)bv)[i & 63];
}

// ---------------- K1: prep (Aqk + small vectors), grid 16x16 ----------------
__global__ __launch_bounds__(256) void prep_kernel(const float* __restrict__ Wq,
                                                   const float* __restrict__ bq,
                                                   const float* __restrict__ Wk,
                                                   const float* __restrict__ bk) {
    __shared__ __align__(16) float Aw[256 * 16];
    __shared__ __align__(16) float Bw[256 * 16];
    __shared__ float s_bq[256], s_bk[256];
    int tid = threadIdx.x;
    int tx = tid & 15, ty = tid >> 4;
    int m0 = blockIdx.y * 16, n0 = blockIdx.x * 16;

    int e0 = tid >> 2, q = tid & 3;
    #pragma unroll
    for (int j = 0; j < 4; j++) {
        int e = e0 + 64 * j;
        float4 a = *(const float4*)(Wq + (size_t)e * D + m0 + q * 4);
        float4 b = *(const float4*)(Wk + (size_t)e * D + n0 + q * 4);
        *(float4*)&Aw[e * 16 + q * 4] = a;
        *(float4*)&Bw[e * 16 + q * 4] = b;
    }
    s_bq[tid] = bq[tid];
    s_bk[tid] = bk[tid];
    __syncthreads();

    float acc = 0.f;
    #pragma unroll 8
    for (int e = 0; e < 256; e++) acc += Aw[e * 16 + ty] * Bw[e * 16 + tx];
    g_Aqk[(m0 + ty) * D + n0 + tx] = acc;

    if (blockIdx.x == 0 && ty == 0) {
        float su = 0.f, sq = 0.f;
        #pragma unroll 8
        for (int e = 0; e < 256; e++) {
            float w = Aw[e * 16 + tx];
            su += s_bk[e] * w;
            sq += w;
        }
        g_u[m0 + tx] = su;
        g_qrs[m0 + tx] = sq;
    }
    if (blockIdx.y == 0 && ty == 1) {
        float sw = 0.f, sk = 0.f;
        #pragma unroll 8
        for (int e = 0; e < 256; e++) {
            float w = Bw[e * 16 + tx];
            sw += s_bq[e] * w;
            sk += w;
        }
        g_wv[n0 + tx] = sw;
        g_ksum[n0 + tx] = sk;
    }
    if (blockIdx.x == 0 && blockIdx.y == 0 && tid < 32) {
        float a0 = 0.f, a1 = 0.f, a2 = 0.f;
        #pragma unroll
        for (int j = 0; j < 8; j++) {
            float qv = s_bq[tid + 32 * j], kv = s_bk[tid + 32 * j];
            a0 += qv * kv; a1 += qv; a2 += kv;
        }
        #pragma unroll
        for (int o = 16; o > 0; o >>= 1) {
            a0 += __shfl_xor_sync(0xffffffffu, a0, o);
            a1 += __shfl_xor_sync(0xffffffffu, a1, o);
            a2 += __shfl_xor_sync(0xffffffffu, a2, o);
        }
        if (tid == 0) { g_scal[0] = a0; g_scal[1] = a1; g_scal[2] = a2; }
    }
}

// ---------------- split-K GEMM: 128m x 64n x 64k per CTA, grid (4,16,4) ----------------
// ASRC: 0 = x last rows * td    1 = g_Z
// BSRC: 0 = g_Aqk (NN)         1 = param B (NT, B[n][k])
// PDST: 0 = store g_Yp slices  1 = red.global.add into Cout
template <int ASRC, int BSRC, int PDST>
__global__ __launch_bounds__(256) void gemm_sk(const float* __restrict__ x,
                                               const float* __restrict__ td,
                                               const float* __restrict__ Bp,
                                               float* __restrict__ Cout) {
    __shared__ __align__(16) float As[KSL * 128];  // [k][m] 32KB
    __shared__ __align__(16) float Bs[KSL * 64];   // [k][n] 16KB
    int tid = threadIdx.x;
    int n0 = blockIdx.x * 64, m0 = blockIdx.y * 128, ks = blockIdx.z * KSL;

    // ---- A fill ----
    {
        int r = tid & 127, kc = (tid >> 7) * 32;
        const float* arow;
        float asc = 1.0f;
        if (ASRC == 0) {
            int gb = m0 + r;
            arow = x + ((size_t)gb * T + (T - 1)) * D;
            asc = td[gb * T + (T - 1)];
        } else {
            arow = g_Z + (size_t)(m0 + r) * D;
        }
        float4 v[8];
        #pragma unroll
        for (int i = 0; i < 8; i++) v[i] = *(const float4*)(arow + ks + kc + i * 4);
        #pragma unroll
        for (int i = 0; i < 8; i++) {
            As[(kc + i * 4 + 0) * 128 + r] = v[i].x * asc;
            As[(kc + i * 4 + 1) * 128 + r] = v[i].y * asc;
            As[(kc + i * 4 + 2) * 128 + r] = v[i].z * asc;
            As[(kc + i * 4 + 3) * 128 + r] = v[i].w * asc;
        }
    }
    // ---- B fill ----
    if (BSRC == 0) {
        int q = tid & 15, kr0 = tid >> 4;
        #pragma unroll
        for (int p = 0; p < 4; p++) {
            int kr = kr0 + p * 16;
            float4 v = *(const float4*)(g_Aqk + (size_t)(ks + kr) * D + n0 + q * 4);
            *(float4*)&Bs[kr * 64 + q * 4] = v;
        }
    } else {
        int nr = tid & 63, kq = (tid >> 6) * 16;
        const float* brow = Bp + (size_t)(n0 + nr) * D + ks + kq;
        float4 v0 = *(const float4*)(brow);
        float4 v1 = *(const float4*)(brow + 4);
        float4 v2 = *(const float4*)(brow + 8);
        float4 v3 = *(const float4*)(brow + 12);
        float vs[16] = {v0.x, v0.y, v0.z, v0.w, v1.x, v1.y, v1.z, v1.w,
                        v2.x, v2.y, v2.z, v2.w, v3.x, v3.y, v3.z, v3.w};
        #pragma unroll
        for (int i = 0; i < 16; i++) Bs[(kq + i) * 64 + nr] = vs[i];
    }
    __syncthreads();

    // ---- inner loop: thread tile 8m x 4n, f32x2 over m-pairs ----
    int tx = tid & 15, ty = tid >> 4;
    u64 acc[4][4] = {};
    #pragma unroll 2
    for (int kk = 0; kk < KSL; kk += 16) {
        #pragma unroll
        for (int k2 = 0; k2 < 16; k2++) {
            int k = kk + k2;
            ulonglong2 a01 = *(const ulonglong2*)&As[k * 128 + ty * 8];
            ulonglong2 a23 = *(const ulonglong2*)&As[k * 128 + ty * 8 + 4];
            float4 b4 = *(const float4*)&Bs[k * 64 + tx * 4];
            u64 b0 = pack_dup(b4.x), b1 = pack_dup(b4.y);
            u64 b2 = pack_dup(b4.z), b3 = pack_dup(b4.w);
            ffma2(acc[0][0], a01.x, b0); ffma2(acc[0][1], a01.x, b1);
            ffma2(acc[0][2], a01.x, b2); ffma2(acc[0][3], a01.x, b3);
            ffma2(acc[1][0], a01.y, b0); ffma2(acc[1][1], a01.y, b1);
            ffma2(acc[1][2], a01.y, b2); ffma2(acc[1][3], a01.y, b3);
            ffma2(acc[2][0], a23.x, b0); ffma2(acc[2][1], a23.x, b1);
            ffma2(acc[2][2], a23.x, b2); ffma2(acc[2][3], a23.x, b3);
            ffma2(acc[3][0], a23.y, b0); ffma2(acc[3][1], a23.y, b1);
            ffma2(acc[3][2], a23.y, b2); ffma2(acc[3][3], a23.y, b3);
        }
    }

    int gn = n0 + tx * 4;
    int gmb = m0 + ty * 8;
    if (PDST == 0) {
        size_t base = ((size_t)blockIdx.z * BATCH + gmb) * D + gn;
        #pragma unroll
        for (int mp = 0; mp < 4; mp++) {
            float2 p0 = unpack2(acc[mp][0]), p1 = unpack2(acc[mp][1]);
            float2 p2 = unpack2(acc[mp][2]), p3 = unpack2(acc[mp][3]);
            *(float4*)&g_Yp[base + (size_t)(2 * mp) * D] = make_float4(p0.x, p1.x, p2.x, p3.x);
            *(float4*)&g_Yp[base + (size_t)(2 * mp + 1) * D] = make_float4(p0.y, p1.y, p2.y, p3.y);
        }
    } else {
        size_t base = (size_t)gmb * D + gn;
        #pragma unroll
        for (int mp = 0; mp < 4; mp++) {
            float2 p0 = unpack2(acc[mp][0]), p1 = unpack2(acc[mp][1]);
            float2 p2 = unpack2(acc[mp][2]), p3 = unpack2(acc[mp][3]);
            redg_v4(Cout + base + (size_t)(2 * mp) * D, p0.x, p1.x, p2.x, p3.x);
            redg_v4(Cout + base + (size_t)(2 * mp + 1) * D, p0.y, p1.y, p2.y, p3.y);
        }
    }
}

// ---------------- K3: attn — mask-filtered, single-shot TMA bulk-copy ----------------
__global__ __launch_bounds__(256, 4) void attn_kernel(const float* __restrict__ x,
                                                      const int* __restrict__ mask,
                                                      const float* __restrict__ td,
                                                      int want) {
    extern __shared__ __align__(128) float sm[];
    u64* mbar = (u64*)sm;
    float* smx = sm + 32;            // 50*256 floats, 128B-aligned
    float* smV = smx + T * D;        // 256
    float* smtd = smV + D;           // 64
    float* smDV = smtd + 64;         // 64 (50,51 hold dU,dQ)
    float* smw = smDV + 64;          // 64
    int* smm = (int*)(smw + 64);     // 64

    int b = blockIdx.x, tid = threadIdx.x;
    int warp = tid >> 5, lane = tid & 31;
    const int XBYTES = T * D * 4;    // 51200

    int mq = __ldg(mask + b * T + (T - 1));
    if (mq != want) return;          // CTA-uniform early exit

    unsigned mbar_a = smem_u32(mbar);
    unsigned smx_a = smem_u32(smx);

    if (tid == 0) {
        asm volatile("mbarrier.init.shared.b64 [%0], 1;" :: "r"(mbar_a) : "memory");
        asm volatile("fence.proxy.async.shared::cta;" ::: "memory");
        asm volatile("mbarrier.arrive.expect_tx.shared.b64 _, [%0], %1;"
                     :: "r"(mbar_a), "r"(XBYTES) : "memory");
        asm volatile("cp.async.bulk.shared::cta.global.mbarrier::complete_tx::bytes "
                     "[%0], [%1], %2, [%3];"
                     :: "r"(smx_a), "l"(x + (size_t)b * T * D), "r"(XBYTES), "r"(mbar_a)
                     : "memory");
    }

    if (mq) {
        int idx = b * D + tid;
        float s = g_wv[tid];
        #pragma unroll
        for (int j = 0; j < NSK; j++) s += g_Yp[(size_t)j * BATCH * D + idx];
        smV[tid] = s;
    } else {
        smV[tid] = g_ksum[tid];
    }
    if (tid < T) {
        smtd[tid] = td[b * T + tid];
        smm[tid] = mask[b * T + tid];
    }
    __syncthreads();

    {
        unsigned done;
        asm volatile(
            "{\n\t.reg .pred p;\n\t"
            "mbarrier.try_wait.parity.acquire.cta.shared::cta.b64 p, [%1], 0;\n\t"
            "selp.b32 %0, 1, 0, p;\n\t}"
            : "=r"(done) : "r"(mbar_a) : "memory");
        if (!done) {
            asm volatile(
                "{\n\t.reg .pred P1;\n\t"
                "WL_%=:\n\t"
                "mbarrier.try_wait.parity.acquire.cta.shared::cta.b64 P1, [%0], 0, 0x989680;\n\t"
                "@P1 bra.uni WD_%=;\n\t"
                "bra.uni WL_%=;\n\t"
                "WD_%=:\n\t}"
                :: "r"(mbar_a) : "memory");
        }
    }

    float4* smx4 = (float4*)smx;
    float4 va = ((const float4*)smV)[lane];
    float4 vb = ((const float4*)smV)[lane + 32];
    for (int s = warp; s < T; s += 8) {
        float4 x1 = smx4[s * 64 + lane];
        float4 x2 = smx4[s * 64 + 32 + lane];
        float dv = dot4(x1, va) + dot4(x2, vb);
        #pragma unroll
        for (int o = 16; o > 0; o >>= 1) dv += __shfl_xor_sync(0xffffffffu, dv, o);
        if (lane == 0) smDV[s] = dv;
    }
    if (warp == 2 || warp == 3) {
        const float4* w4 = (warp == 2) ? (const float4*)g_u : (const float4*)g_qrs;
        float4 x1 = smx4[(T - 1) * 64 + lane];
        float4 x2 = smx4[(T - 1) * 64 + 32 + lane];
        float dv = dot4(x1, __ldg(w4 + lane)) + dot4(x2, __ldg(w4 + lane + 32));
        #pragma unroll
        for (int o = 16; o > 0; o >>= 1) dv += __shfl_xor_sync(0xffffffffu, dv, o);
        if (lane == 0) smDV[T + (warp - 2)] = dv;
    }
    __syncthreads();

    if (warp == 0) {
        float tdl = smtd[T - 1];
        float s1b = tdl * smDV[T] + g_scal[0];
        float s2b = tdl * smDV[T + 1] + g_scal[1];
        float bksum = g_scal[2];
        float v1 = -3.0e38f, v2 = -3.0e38f;
        if (lane < T) {
            int ms = smm[lane];
            float tds = smtd[lane];
            if (mq) v1 = ms ? (tds * smDV[lane] + s1b) : (NEGC * s2b);
            else    v1 = ms ? (NEGC * (tds * smDV[lane] + bksum)) : (NEGC * NEGC * (float)D);
            v1 *= INV_SQRT_D;
        }
        if (lane + 32 < T) {
            int s = lane + 32;
            int ms = smm[s];
            float tds = smtd[s];
            if (mq) v2 = ms ? (tds * smDV[s] + s1b) : (NEGC * s2b);
            else    v2 = ms ? (NEGC * (tds * smDV[s] + bksum)) : (NEGC * NEGC * (float)D);
            v2 *= INV_SQRT_D;
        }
        float m = fmaxf(v1, v2);
        #pragma unroll
        for (int o = 16; o > 0; o >>= 1) m = fmaxf(m, __shfl_xor_sync(0xffffffffu, m, o));
        float e1 = (lane < T) ? expf(v1 - m) : 0.f;
        float e2 = (lane + 32 < T) ? expf(v2 - m) : 0.f;
        float es = e1 + e2;
        #pragma unroll
        for (int o = 16; o > 0; o >>= 1) es += __shfl_xor_sync(0xffffffffu, es, o);
        float inv = 1.0f / es;
        if (lane < T) smw[lane] = e1 * inv * smtd[lane];
        if (lane + 32 < T) smw[lane + 32] = e2 * inv * smtd[lane + 32];
    }
    __syncthreads();

    int g = tid >> 6, q = tid & 63;
    float4 acc = make_float4(0.f, 0.f, 0.f, 0.f);
    for (int s = g; s < T; s += 4) {
        float w = smw[s];
        float4 xv = smx4[s * 64 + q];
        acc.x += w * xv.x; acc.y += w * xv.y; acc.z += w * xv.z; acc.w += w * xv.w;
    }
    __syncthreads();
    smx4[g * 64 + q] = acc;
    __syncthreads();
    if (tid < 64) {
        float4 p0 = smx4[tid], p1 = smx4[64 + tid];
        float4 p2 = smx4[128 + tid], p3 = smx4[192 + tid];
        float4 r = make_float4(p0.x + p1.x + p2.x + p3.x, p0.y + p1.y + p2.y + p3.y,
                               p0.z + p1.z + p2.z + p3.z, p0.w + p1.w + p2.w + p3.w);
        ((float4*)(g_Z + (size_t)b * D))[tid] = r;
    }
}

// ---------------- launch: overlap graph + REDG epilogue ----------------
extern "C" void kernel_launch(void* const* d_in, const int* in_sizes, int n_in,
                              void* d_out, int out_size) {
    const float* x = (const float*)d_in[0];
    const int* mask = (const int*)d_in[1];
    const float* td = (const float*)d_in[2];
    const float* Wq = (const float*)d_in[3];
    const float* bq = (const float*)d_in[4];
    const float* Wk = (const float*)d_in[5];
    const float* bk = (const float*)d_in[6];
    const float* Wv = (const float*)d_in[7];
    const float* bv = (const float*)d_in[8];
    float* out = (float*)d_out;

    const int attn_smem = (32 + T * D + D + 64 + 64 + 64 + 64) * 4;  // ~53.4 KB
    cudaFuncSetAttribute(attn_kernel, cudaFuncAttributeMaxDynamicSharedMemorySize, attn_smem);

    cudaStream_t s1 = g_infra.s1;
    dim3 gsk(4, 16, NSK);

    // fork s1 from capture stream
    cudaEventRecord(g_infra.evRoot, 0);
    cudaStreamWaitEvent(s1, g_infra.evRoot, 0);
    init_out<<<BATCH * D / 4 / 256, 256, 0, s1>>>(bv, out);   // bias prefill, hidden

    // s0: prep -> gemm_Y
    prep_kernel<<<dim3(16, 16), 256>>>(Wq, bq, Wk, bk);
    cudaEventRecord(g_infra.evP, 0);
    gemm_sk<0, 0, 0><<<gsk, 256>>>(x, td, nullptr, nullptr);  // Y partials
    cudaEventRecord(g_infra.ev0, 0);

    // s1: attn mq==0 (needs only prep) overlaps gemm_Y; attn mq==1 after Y
    cudaStreamWaitEvent(s1, g_infra.evP, 0);
    attn_kernel<<<BATCH, 256, attn_smem, s1>>>(x, mask, td, 0);
    cudaStreamWaitEvent(s1, g_infra.ev0, 0);
    attn_kernel<<<BATCH, 256, attn_smem, s1>>>(x, mask, td, 1);
    cudaEventRecord(g_infra.ev1, s1);

    // s0: REDG out-GEMM after all Z ready (ev1 also orders init_out on s1)
    cudaStreamWaitEvent(0, g_infra.ev1, 0);
    gemm_sk<1, 1, 1><<<gsk, 256>>>(nullptr, nullptr, Wv, out);  // REDG into out
}

// round 17
// speedup vs baseline: 1.1337x; 1.0005x over previous
#include <cuda_runtime.h>
#include <math.h>

#define BATCH 2048
#define T 50
#define D 256
#define NEGC (-100000.0f)
#define INV_SQRT_D 0.0625f
#define NSK 4            // split-K slices
#define KSL 64           // k per slice

typedef unsigned long long u64;

// ---------------- device scratch ----------------
__device__ float g_Aqk[D * D];
__device__ float g_u[D];
__device__ float g_qrs[D];
__device__ float g_wv[D];
__device__ float g_ksum[D];
__device__ float g_scal[3];
__device__ float g_Z[BATCH * D];
__device__ float g_Yp[NSK * BATCH * D];   // split-K partials of Y

// ---------------- stream/event infra (created at load, before capture) ----------------
namespace {
struct Infra {
    cudaStream_t s1;
    cudaEvent_t evRoot, evP, ev0, ev1;
    Infra() {
        cudaStreamCreateWithFlags(&s1, cudaStreamNonBlocking);
        cudaEventCreateWithFlags(&evRoot, cudaEventDisableTiming);
        cudaEventCreateWithFlags(&evP, cudaEventDisableTiming);
        cudaEventCreateWithFlags(&ev0, cudaEventDisableTiming);
        cudaEventCreateWithFlags(&ev1, cudaEventDisableTiming);
    }
};
Infra g_infra;
}

// ---------------- helpers ----------------
__device__ __forceinline__ void ffma2(u64& d, u64 a, u64 b) {
    asm("fma.rn.f32x2 %0, %1, %2, %0;" : "+l"(d) : "l"(a), "l"(b));
}
__device__ __forceinline__ float2 unpack2(u64 v) {
    float2 r;
    asm("mov.b64 {%0, %1}, %2;" : "=f"(r.x), "=f"(r.y) : "l"(v));
    return r;
}
__device__ __forceinline__ u64 pack_dup(float v) {
    u64 r;
    asm("mov.b64 %0, {%1, %1};" : "=l"(r) : "f"(v));
    return r;
}
__device__ __forceinline__ float dot4(float4 a, float4 b) {
    return a.x * b.x + a.y * b.y + a.z * b.z + a.w * b.w;
}
__device__ __forceinline__ unsigned smem_u32(const void* p) {
    unsigned a;
    asm("{ .reg .u64 t; cvta.to.shared.u64 t, %1; cvt.u32.u64 %0, t; }" : "=r"(a) : "l"(p));
    return a;
}
__device__ __forceinline__ void redg_v4(float* p, float a, float b, float c, float d) {
    asm volatile("red.global.add.v4.f32 [%0], {%1, %2, %3, %4};"
                 :: "l"(p), "f"(a), "f"(b), "f"(c), "f"(d) : "memory");
}

// ---------------- K0: init out with bias (overlapped on s1) ----------------
__global__ __launch_bounds__(256) void init_out(const float* __restrict__ bv,
                                                float* __restrict__ out) {
    int i = blockIdx.x * 256 + threadIdx.x;
    ((float4*)out)[i] = ((const float4*)bv)[i & 63];
}

// ---------------- K1: prep (Aqk + small vectors), grid 16x16 ----------------
__global__ __launch_bounds__(256) void prep_kernel(const float* __restrict__ Wq,
                                                   const float* __restrict__ bq,
                                                   const float* __restrict__ Wk,
                                                   const float* __restrict__ bk) {
    __shared__ __align__(16) float Aw[256 * 16];
    __shared__ __align__(16) float Bw[256 * 16];
    __shared__ float s_bq[256], s_bk[256];
    int tid = threadIdx.x;
    int tx = tid & 15, ty = tid >> 4;
    int m0 = blockIdx.y * 16, n0 = blockIdx.x * 16;

    int e0 = tid >> 2, q = tid & 3;
    #pragma unroll
    for (int j = 0; j < 4; j++) {
        int e = e0 + 64 * j;
        float4 a = *(const float4*)(Wq + (size_t)e * D + m0 + q * 4);
        float4 b = *(const float4*)(Wk + (size_t)e * D + n0 + q * 4);
        *(float4*)&Aw[e * 16 + q * 4] = a;
        *(float4*)&Bw[e * 16 + q * 4] = b;
    }
    s_bq[tid] = bq[tid];
    s_bk[tid] = bk[tid];
    __syncthreads();

    float acc = 0.f;
    #pragma unroll 8
    for (int e = 0; e < 256; e++) acc += Aw[e * 16 + ty] * Bw[e * 16 + tx];
    g_Aqk[(m0 + ty) * D + n0 + tx] = acc;

    if (blockIdx.x == 0 && ty == 0) {
        float su = 0.f, sq = 0.f;
        #pragma unroll 8
        for (int e = 0; e < 256; e++) {
            float w = Aw[e * 16 + tx];
            su += s_bk[e] * w;
            sq += w;
        }
        g_u[m0 + tx] = su;
        g_qrs[m0 + tx] = sq;
    }
    if (blockIdx.y == 0 && ty == 1) {
        float sw = 0.f, sk = 0.f;
        #pragma unroll 8
        for (int e = 0; e < 256; e++) {
            float w = Bw[e * 16 + tx];
            sw += s_bq[e] * w;
            sk += w;
        }
        g_wv[n0 + tx] = sw;
        g_ksum[n0 + tx] = sk;
    }
    if (blockIdx.x == 0 && blockIdx.y == 0 && tid < 32) {
        float a0 = 0.f, a1 = 0.f, a2 = 0.f;
        #pragma unroll
        for (int j = 0; j < 8; j++) {
            float qv = s_bq[tid + 32 * j], kv = s_bk[tid + 32 * j];
            a0 += qv * kv; a1 += qv; a2 += kv;
        }
        #pragma unroll
        for (int o = 16; o > 0; o >>= 1) {
            a0 += __shfl_xor_sync(0xffffffffu, a0, o);
            a1 += __shfl_xor_sync(0xffffffffu, a1, o);
            a2 += __shfl_xor_sync(0xffffffffu, a2, o);
        }
        if (tid == 0) { g_scal[0] = a0; g_scal[1] = a1; g_scal[2] = a2; }
    }
}

// ---------------- split-K GEMM: 128m x 64n x 64k per CTA, grid (4,16,4) ----------------
// ASRC: 0 = x last rows * td    1 = g_Z
// BSRC: 0 = g_Aqk (NN)         1 = param B (NT, B[n][k])
// PDST: 0 = store g_Yp slices  1 = red.global.add into Cout
template <int ASRC, int BSRC, int PDST>
__global__ __launch_bounds__(256) void gemm_sk(const float* __restrict__ x,
                                               const float* __restrict__ td,
                                               const float* __restrict__ Bp,
                                               float* __restrict__ Cout) {
    __shared__ __align__(16) float As[KSL * 128];  // [k][m] 32KB
    __shared__ __align__(16) float Bs[KSL * 64];   // [k][n] 16KB
    int tid = threadIdx.x;
    int n0 = blockIdx.x * 64, m0 = blockIdx.y * 128, ks = blockIdx.z * KSL;

    // ---- A fill ----
    {
        int r = tid & 127, kc = (tid >> 7) * 32;
        const float* arow;
        float asc = 1.0f;
        if (ASRC == 0) {
            int gb = m0 + r;
            arow = x + ((size_t)gb * T + (T - 1)) * D;
            asc = td[gb * T + (T - 1)];
        } else {
            arow = g_Z + (size_t)(m0 + r) * D;
        }
        float4 v[8];
        #pragma unroll
        for (int i = 0; i < 8; i++) v[i] = *(const float4*)(arow + ks + kc + i * 4);
        #pragma unroll
        for (int i = 0; i < 8; i++) {
            As[(kc + i * 4 + 0) * 128 + r] = v[i].x * asc;
            As[(kc + i * 4 + 1) * 128 + r] = v[i].y * asc;
            As[(kc + i * 4 + 2) * 128 + r] = v[i].z * asc;
            As[(kc + i * 4 + 3) * 128 + r] = v[i].w * asc;
        }
    }
    // ---- B fill ----
    if (BSRC == 0) {
        int q = tid & 15, kr0 = tid >> 4;
        #pragma unroll
        for (int p = 0; p < 4; p++) {
            int kr = kr0 + p * 16;
            float4 v = *(const float4*)(g_Aqk + (size_t)(ks + kr) * D + n0 + q * 4);
            *(float4*)&Bs[kr * 64 + q * 4] = v;
        }
    } else {
        int nr = tid & 63, kq = (tid >> 6) * 16;
        const float* brow = Bp + (size_t)(n0 + nr) * D + ks + kq;
        float4 v0 = *(const float4*)(brow);
        float4 v1 = *(const float4*)(brow + 4);
        float4 v2 = *(const float4*)(brow + 8);
        float4 v3 = *(const float4*)(brow + 12);
        float vs[16] = {v0.x, v0.y, v0.z, v0.w, v1.x, v1.y, v1.z, v1.w,
                        v2.x, v2.y, v2.z, v2.w, v3.x, v3.y, v3.z, v3.w};
        #pragma unroll
        for (int i = 0; i < 16; i++) Bs[(kq + i) * 64 + nr] = vs[i];
    }
    __syncthreads();

    // ---- inner loop: thread tile 8m x 4n, f32x2 over m-pairs ----
    int tx = tid & 15, ty = tid >> 4;
    u64 acc[4][4] = {};
    #pragma unroll 2
    for (int kk = 0; kk < KSL; kk += 16) {
        #pragma unroll
        for (int k2 = 0; k2 < 16; k2++) {
            int k = kk + k2;
            ulonglong2 a01 = *(const ulonglong2*)&As[k * 128 + ty * 8];
            ulonglong2 a23 = *(const ulonglong2*)&As[k * 128 + ty * 8 + 4];
            float4 b4 = *(const float4*)&Bs[k * 64 + tx * 4];
            u64 b0 = pack_dup(b4.x), b1 = pack_dup(b4.y);
            u64 b2 = pack_dup(b4.z), b3 = pack_dup(b4.w);
            ffma2(acc[0][0], a01.x, b0); ffma2(acc[0][1], a01.x, b1);
            ffma2(acc[0][2], a01.x, b2); ffma2(acc[0][3], a01.x, b3);
            ffma2(acc[1][0], a01.y, b0); ffma2(acc[1][1], a01.y, b1);
            ffma2(acc[1][2], a01.y, b2); ffma2(acc[1][3], a01.y, b3);
            ffma2(acc[2][0], a23.x, b0); ffma2(acc[2][1], a23.x, b1);
            ffma2(acc[2][2], a23.x, b2); ffma2(acc[2][3], a23.x, b3);
            ffma2(acc[3][0], a23.y, b0); ffma2(acc[3][1], a23.y, b1);
            ffma2(acc[3][2], a23.y, b2); ffma2(acc[3][3], a23.y, b3);
        }
    }

    int gn = n0 + tx * 4;
    int gmb = m0 + ty * 8;
    if (PDST == 0) {
        size_t base = ((size_t)blockIdx.z * BATCH + gmb) * D + gn;
        #pragma unroll
        for (int mp = 0; mp < 4; mp++) {
            float2 p0 = unpack2(acc[mp][0]), p1 = unpack2(acc[mp][1]);
            float2 p2 = unpack2(acc[mp][2]), p3 = unpack2(acc[mp][3]);
            *(float4*)&g_Yp[base + (size_t)(2 * mp) * D] = make_float4(p0.x, p1.x, p2.x, p3.x);
            *(float4*)&g_Yp[base + (size_t)(2 * mp + 1) * D] = make_float4(p0.y, p1.y, p2.y, p3.y);
        }
    } else {
        size_t base = (size_t)gmb * D + gn;
        #pragma unroll
        for (int mp = 0; mp < 4; mp++) {
            float2 p0 = unpack2(acc[mp][0]), p1 = unpack2(acc[mp][1]);
            float2 p2 = unpack2(acc[mp][2]), p3 = unpack2(acc[mp][3]);
            redg_v4(Cout + base + (size_t)(2 * mp) * D, p0.x, p1.x, p2.x, p3.x);
            redg_v4(Cout + base + (size_t)(2 * mp + 1) * D, p0.y, p1.y, p2.y, p3.y);
        }
    }
}

// ---------------- K3: attn — mask-filtered, TMA bulk-copy, ILP dots ----------------
__global__ __launch_bounds__(256, 4) void attn_kernel(const float* __restrict__ x,
                                                      const int* __restrict__ mask,
                                                      const float* __restrict__ td,
                                                      int want) {
    extern __shared__ __align__(128) float sm[];
    u64* mbar = (u64*)sm;
    float* smx = sm + 32;            // 50*256 floats, 128B-aligned
    float* smV = smx + T * D;        // 256
    float* smtd = smV + D;           // 64
    float* smDV = smtd + 64;         // 64 (50,51 hold dU,dQ)
    float* smw = smDV + 64;          // 64
    int* smm = (int*)(smw + 64);     // 64

    int b = blockIdx.x, tid = threadIdx.x;
    int warp = tid >> 5, lane = tid & 31;
    const int XBYTES = T * D * 4;    // 51200

    int mq = __ldg(mask + b * T + (T - 1));
    if (mq != want) return;          // CTA-uniform early exit

    unsigned mbar_a = smem_u32(mbar);
    unsigned smx_a = smem_u32(smx);

    if (tid == 0) {
        asm volatile("mbarrier.init.shared.b64 [%0], 1;" :: "r"(mbar_a) : "memory");
        asm volatile("fence.proxy.async.shared::cta;" ::: "memory");
        asm volatile("mbarrier.arrive.expect_tx.shared.b64 _, [%0], %1;"
                     :: "r"(mbar_a), "r"(XBYTES) : "memory");
        asm volatile("cp.async.bulk.shared::cta.global.mbarrier::complete_tx::bytes "
                     "[%0], [%1], %2, [%3];"
                     :: "r"(smx_a), "l"(x + (size_t)b * T * D), "r"(XBYTES), "r"(mbar_a)
                     : "memory");
    }

    if (mq) {
        int idx = b * D + tid;
        float s = g_wv[tid];
        #pragma unroll
        for (int j = 0; j < NSK; j++) s += g_Yp[(size_t)j * BATCH * D + idx];
        smV[tid] = s;
    } else {
        smV[tid] = g_ksum[tid];
    }
    if (tid < T) {
        smtd[tid] = td[b * T + tid];
        smm[tid] = mask[b * T + tid];
    }
    __syncthreads();

    {
        unsigned done;
        asm volatile(
            "{\n\t.reg .pred p;\n\t"
            "mbarrier.try_wait.parity.acquire.cta.shared::cta.b64 p, [%1], 0;\n\t"
            "selp.b32 %0, 1, 0, p;\n\t}"
            : "=r"(done) : "r"(mbar_a) : "memory");
        if (!done) {
            asm volatile(
                "{\n\t.reg .pred P1;\n\t"
                "WL_%=:\n\t"
                "mbarrier.try_wait.parity.acquire.cta.shared::cta.b64 P1, [%0], 0, 0x989680;\n\t"
                "@P1 bra.uni WD_%=;\n\t"
                "bra.uni WL_%=;\n\t"
                "WD_%=:\n\t}"
                :: "r"(mbar_a) : "memory");
        }
    }

    float4* smx4 = (float4*)smx;
    float4 va = ((const float4*)smV)[lane];
    float4 vb = ((const float4*)smV)[lane + 32];

    // dots: fully unrolled 4 x 2 independent shuffle chains per warp
    #pragma unroll
    for (int jp = 0; jp < 4; jp++) {
        int s0 = warp + 16 * jp;
        int s1 = s0 + 8;
        int s0c = (s0 < T) ? s0 : 0;
        int s1c = (s1 < T) ? s1 : 0;
        float4 a1 = smx4[s0c * 64 + lane];
        float4 a2 = smx4[s0c * 64 + 32 + lane];
        float4 c1 = smx4[s1c * 64 + lane];
        float4 c2 = smx4[s1c * 64 + 32 + lane];
        float d0 = dot4(a1, va) + dot4(a2, vb);
        float d1 = dot4(c1, va) + dot4(c2, vb);
        #pragma unroll
        for (int o = 16; o > 0; o >>= 1) {
            d0 += __shfl_xor_sync(0xffffffffu, d0, o);
            d1 += __shfl_xor_sync(0xffffffffu, d1, o);
        }
        if (lane == 0) {
            if (s0 < T) smDV[s0] = d0;
            if (s1 < T) smDV[s1] = d1;
        }
    }
    if (warp == 2 || warp == 3) {
        const float4* w4 = (warp == 2) ? (const float4*)g_u : (const float4*)g_qrs;
        float4 x1 = smx4[(T - 1) * 64 + lane];
        float4 x2 = smx4[(T - 1) * 64 + 32 + lane];
        float dv = dot4(x1, __ldg(w4 + lane)) + dot4(x2, __ldg(w4 + lane + 32));
        #pragma unroll
        for (int o = 16; o > 0; o >>= 1) dv += __shfl_xor_sync(0xffffffffu, dv, o);
        if (lane == 0) smDV[T + (warp - 2)] = dv;
    }
    __syncthreads();

    if (warp == 0) {
        float tdl = smtd[T - 1];
        float s1b = tdl * smDV[T] + g_scal[0];
        float s2b = tdl * smDV[T + 1] + g_scal[1];
        float bksum = g_scal[2];
        float v1 = -3.0e38f, v2 = -3.0e38f;
        if (lane < T) {
            int ms = smm[lane];
            float tds = smtd[lane];
            if (mq) v1 = ms ? (tds * smDV[lane] + s1b) : (NEGC * s2b);
            else    v1 = ms ? (NEGC * (tds * smDV[lane] + bksum)) : (NEGC * NEGC * (float)D);
            v1 *= INV_SQRT_D;
        }
        if (lane + 32 < T) {
            int s = lane + 32;
            int ms = smm[s];
            float tds = smtd[s];
            if (mq) v2 = ms ? (tds * smDV[s] + s1b) : (NEGC * s2b);
            else    v2 = ms ? (NEGC * (tds * smDV[s] + bksum)) : (NEGC * NEGC * (float)D);
            v2 *= INV_SQRT_D;
        }
        float m = fmaxf(v1, v2);
        #pragma unroll
        for (int o = 16; o > 0; o >>= 1) m = fmaxf(m, __shfl_xor_sync(0xffffffffu, m, o));
        float e1 = (lane < T) ? expf(v1 - m) : 0.f;
        float e2 = (lane + 32 < T) ? expf(v2 - m) : 0.f;
        float es = e1 + e2;
        #pragma unroll
        for (int o = 16; o > 0; o >>= 1) es += __shfl_xor_sync(0xffffffffu, es, o);
        float inv = 1.0f / es;
        if (lane < T) smw[lane] = e1 * inv * smtd[lane];
        if (lane + 32 < T) smw[lane + 32] = e2 * inv * smtd[lane + 32];
    }
    __syncthreads();

    int g = tid >> 6, q = tid & 63;
    float4 acc = make_float4(0.f, 0.f, 0.f, 0.f);
    for (int s = g; s < T; s += 4) {
        float w = smw[s];
        float4 xv = smx4[s * 64 + q];
        acc.x += w * xv.x; acc.y += w * xv.y; acc.z += w * xv.z; acc.w += w * xv.w;
    }
    __syncthreads();
    smx4[g * 64 + q] = acc;
    __syncthreads();
    if (tid < 64) {
        float4 p0 = smx4[tid], p1 = smx4[64 + tid];
        float4 p2 = smx4[128 + tid], p3 = smx4[192 + tid];
        float4 r = make_float4(p0.x + p1.x + p2.x + p3.x, p0.y + p1.y + p2.y + p3.y,
                               p0.z + p1.z + p2.z + p3.z, p0.w + p1.w + p2.w + p3.w);
        ((float4*)(g_Z + (size_t)b * D))[tid] = r;
    }
}

// ---------------- launch: overlap graph + REDG epilogue ----------------
extern "C" void kernel_launch(void* const* d_in, const int* in_sizes, int n_in,
                              void* d_out, int out_size) {
    const float* x = (const float*)d_in[0];
    const int* mask = (const int*)d_in[1];
    const float* td = (const float*)d_in[2];
    const float* Wq = (const float*)d_in[3];
    const float* bq = (const float*)d_in[4];
    const float* Wk = (const float*)d_in[5];
    const float* bk = (const float*)d_in[6];
    const float* Wv = (const float*)d_in[7];
    const float* bv = (const float*)d_in[8];
    float* out = (float*)d_out;

    const int attn_smem = (32 + T * D + D + 64 + 64 + 64 + 64) * 4;  // ~53.4 KB
    cudaFuncSetAttribute(attn_kernel, cudaFuncAttributeMaxDynamicSharedMemorySize, attn_smem);

    cudaStream_t s1 = g_infra.s1;
    dim3 gsk(4, 16, NSK);

    // fork s1 from capture stream
    cudaEventRecord(g_infra.evRoot, 0);
    cudaStreamWaitEvent(s1, g_infra.evRoot, 0);
    init_out<<<BATCH * D / 4 / 256, 256, 0, s1>>>(bv, out);   // bias prefill, hidden

    // s0: prep -> gemm_Y
    prep_kernel<<<dim3(16, 16), 256>>>(Wq, bq, Wk, bk);
    cudaEventRecord(g_infra.evP, 0);
    gemm_sk<0, 0, 0><<<gsk, 256>>>(x, td, nullptr, nullptr);  // Y partials
    cudaEventRecord(g_infra.ev0, 0);

    // s1: attn mq==0 (needs only prep) overlaps gemm_Y; attn mq==1 after Y
    cudaStreamWaitEvent(s1, g_infra.evP, 0);
    attn_kernel<<<BATCH, 256, attn_smem, s1>>>(x, mask, td, 0);
    cudaStreamWaitEvent(s1, g_infra.ev0, 0);
    attn_kernel<<<BATCH, 256, attn_smem, s1>>>(x, mask, td, 1);
    cudaEventRecord(g_infra.ev1, s1);

    // s0: REDG out-GEMM after all Z ready (ev1 also orders init_out on s1)
    cudaStreamWaitEvent(0, g_infra.ev1, 0);
    gemm_sk<1, 1, 1><<<gsk, 256>>>(nullptr, nullptr, Wv, out);  // REDG into out
}